// round 1
// baseline (speedup 1.0000x reference)
#include <cuda_runtime.h>
#include <cuda_bf16.h>
#include <cstdint>

// Problem constants
#define NN   100000
#define IND  128
#define HID  128
#define OUTD 128
#define RR   8
#define EE   75000

// Scratch (device globals — no allocation allowed)
__device__ float g_h [(size_t)NN * HID];
__device__ float g_h2[(size_t)NN * HID];
__device__ float g_agg[(size_t)RR * NN * HID];

// ---------------------------------------------------------------------------
// Generic multi-segment GEMM:
//   C[m, :] = act( bias + sum_{seg} A_seg[m, 0:128] @ B_seg[0:128, 0:128] )
// seg 0 = (A0, B0); segs 1..nExtra = (A1 + (s-1)*strideA1, B1 + (s-1)*strideB1)
// BM=BN=128, BK=16, 256 threads, 8x8 microtile per thread.
// ---------------------------------------------------------------------------
template <bool RELU>
__global__ void __launch_bounds__(256)
gemm_multi(const float* __restrict__ A0, const float* __restrict__ B0,
           const float* __restrict__ A1, const float* __restrict__ B1,
           int nExtra, size_t strideA1, size_t strideB1,
           const float* __restrict__ bias,
           float* __restrict__ C, int M)
{
    constexpr int BM = 128, BN = 128, BK = 16;
    __shared__ float As[BK][BM];
    __shared__ float Bs[BK][BN];

    const int block_row = blockIdx.x * BM;
    const int tid = threadIdx.x;
    const int tx = tid & 15;   // 16 col-groups
    const int ty = tid >> 4;   // 16 row-groups

    float acc[8][8];
#pragma unroll
    for (int i = 0; i < 8; i++)
#pragma unroll
        for (int j = 0; j < 8; j++) acc[i][j] = 0.0f;

    for (int seg = 0; seg <= nExtra; seg++) {
        const float* __restrict__ A = (seg == 0) ? A0 : (A1 + (size_t)(seg - 1) * strideA1);
        const float* __restrict__ B = (seg == 0) ? B0 : (B1 + (size_t)(seg - 1) * strideB1);

#pragma unroll
        for (int k0 = 0; k0 < 128; k0 += BK) {
            // Load A tile (transposed into As[k][m]) : 128 rows x 16 k = 512 float4
#pragma unroll
            for (int l = 0; l < 2; l++) {
                int idx = tid + l * 256;        // 0..511
                int row = idx >> 2;             // 0..127
                int k4  = (idx & 3) * 4;        // 0,4,8,12
                float4 v = make_float4(0.f, 0.f, 0.f, 0.f);
                int grow = block_row + row;
                if (grow < M)
                    v = *reinterpret_cast<const float4*>(&A[(size_t)grow * 128 + k0 + k4]);
                As[k4 + 0][row] = v.x;
                As[k4 + 1][row] = v.y;
                As[k4 + 2][row] = v.z;
                As[k4 + 3][row] = v.w;
            }
            // Load B tile (Bs[k][n]) : 16 k-rows x 128 cols = 512 float4
#pragma unroll
            for (int l = 0; l < 2; l++) {
                int idx = tid + l * 256;
                int kr = idx >> 5;              // 0..15
                int c4 = (idx & 31) * 4;        // 0..124
                float4 v = *reinterpret_cast<const float4*>(&B[(size_t)(k0 + kr) * 128 + c4]);
                *reinterpret_cast<float4*>(&Bs[kr][c4]) = v;
            }
            __syncthreads();

#pragma unroll
            for (int kk = 0; kk < BK; kk++) {
                float a[8], b[8];
                float4 av0 = *reinterpret_cast<const float4*>(&As[kk][ty * 8]);
                float4 av1 = *reinterpret_cast<const float4*>(&As[kk][ty * 8 + 4]);
                float4 bv0 = *reinterpret_cast<const float4*>(&Bs[kk][tx * 8]);
                float4 bv1 = *reinterpret_cast<const float4*>(&Bs[kk][tx * 8 + 4]);
                a[0]=av0.x; a[1]=av0.y; a[2]=av0.z; a[3]=av0.w;
                a[4]=av1.x; a[5]=av1.y; a[6]=av1.z; a[7]=av1.w;
                b[0]=bv0.x; b[1]=bv0.y; b[2]=bv0.z; b[3]=bv0.w;
                b[4]=bv1.x; b[5]=bv1.y; b[6]=bv1.z; b[7]=bv1.w;
#pragma unroll
                for (int i = 0; i < 8; i++)
#pragma unroll
                    for (int j = 0; j < 8; j++)
                        acc[i][j] = fmaf(a[i], b[j], acc[i][j]);
            }
            __syncthreads();
        }
    }

    // Epilogue: bias (+ReLU), vectorized store
#pragma unroll
    for (int i = 0; i < 8; i++) {
        int grow = block_row + ty * 8 + i;
        if (grow >= M) continue;
#pragma unroll
        for (int j = 0; j < 8; j += 4) {
            int col = tx * 8 + j;
            float4 v;
            v.x = acc[i][j + 0] + bias[col + 0];
            v.y = acc[i][j + 1] + bias[col + 1];
            v.z = acc[i][j + 2] + bias[col + 2];
            v.w = acc[i][j + 3] + bias[col + 3];
            if (RELU) {
                v.x = fmaxf(v.x, 0.f); v.y = fmaxf(v.y, 0.f);
                v.z = fmaxf(v.z, 0.f); v.w = fmaxf(v.w, 0.f);
            }
            *reinterpret_cast<float4*>(&C[(size_t)grow * 128 + col]) = v;
        }
    }
}

// ---------------------------------------------------------------------------
// Zero the aggregation buffer (grid-stride, float4)
// ---------------------------------------------------------------------------
__global__ void zero_agg_kernel()
{
    size_t total4 = (size_t)RR * NN * HID / 4;
    float4* p = reinterpret_cast<float4*>(g_agg);
    for (size_t i = (size_t)blockIdx.x * blockDim.x + threadIdx.x;
         i < total4;
         i += (size_t)gridDim.x * blockDim.x)
        p[i] = make_float4(0.f, 0.f, 0.f, 0.f);
}

// ---------------------------------------------------------------------------
// Edge scatter: agg[r][dst] += w * h[src]   (1 warp per edge, float4 gather)
// ---------------------------------------------------------------------------
__global__ void __launch_bounds__(256)
scatter_kernel(const float* __restrict__ h,
               const int* __restrict__ src,
               const int* __restrict__ dst,
               const float* __restrict__ w)
{
    int warp = (blockIdx.x * blockDim.x + threadIdx.x) >> 5;
    int lane = threadIdx.x & 31;
    if (warp >= RR * EE) return;

    int s = src[warp];
    int d = dst[warp];
    float wt = w[warp];
    int r = warp / EE;

    float4 hv = reinterpret_cast<const float4*>(h + (size_t)s * HID)[lane];
    float* out = g_agg + (size_t)r * NN * HID + (size_t)d * HID + lane * 4;
    atomicAdd(out + 0, hv.x * wt);
    atomicAdd(out + 1, hv.y * wt);
    atomicAdd(out + 2, hv.z * wt);
    atomicAdd(out + 3, hv.w * wt);
}

// ---------------------------------------------------------------------------
// Launch
// ---------------------------------------------------------------------------
static float* sym_addr(const void* sym)
{
    void* p = nullptr;
    cudaGetSymbolAddress(&p, sym);
    return reinterpret_cast<float*>(p);
}

extern "C" void kernel_launch(void* const* d_in, const int* in_sizes, int n_in,
                              void* d_out, int out_size)
{
    // metadata order: x, edge_src, edge_dst, edge_w, W_in, b_in, W_rel,
    //                 W_self, b_self, W_out, b_out
    const float* x        = (const float*)d_in[0];
    const int*   edge_src = (const int*)  d_in[1];
    const int*   edge_dst = (const int*)  d_in[2];
    const float* edge_w   = (const float*)d_in[3];
    const float* W_in     = (const float*)d_in[4];
    const float* b_in     = (const float*)d_in[5];
    const float* W_rel    = (const float*)d_in[6];
    const float* W_self   = (const float*)d_in[7];
    const float* b_self   = (const float*)d_in[8];
    const float* W_out    = (const float*)d_in[9];
    const float* b_out    = (const float*)d_in[10];
    float* out = (float*)d_out;

    float* h   = sym_addr(g_h);
    float* h2  = sym_addr(g_h2);
    float* agg = sym_addr(g_agg);

    const int gemm_grid = (NN + 127) / 128;   // 782

    // Zero aggregation buffers (runs concurrently-safe before scatter)
    zero_agg_kernel<<<8192, 256>>>();

    // Layer 1: h = relu(x @ W_in + b_in)
    gemm_multi<true><<<gemm_grid, 256>>>(x, W_in, nullptr, nullptr, 0, 0, 0,
                                         b_in, h, NN);

    // Scatter: agg[r][dst] += w * h[src]
    {
        long long warps = (long long)RR * EE;                // 600000
        int blocks = (int)((warps * 32 + 255) / 256);        // 75000
        scatter_kernel<<<blocks, 256>>>(h, edge_src, edge_dst, edge_w);
    }

    // Layer 2: h2 = relu(h @ W_self + sum_r agg_r @ W_rel[r] + b_self)
    gemm_multi<true><<<gemm_grid, 256>>>(h, W_self, agg, W_rel,
                                         RR,
                                         (size_t)NN * HID,       // strideA1
                                         (size_t)HID * HID,      // strideB1
                                         b_self, h2, NN);

    // Output: out = h2 @ W_out + b_out
    gemm_multi<false><<<gemm_grid, 256>>>(h2, W_out, nullptr, nullptr, 0, 0, 0,
                                          b_out, out, NN);
}

// round 7
// speedup vs baseline: 1.9669x; 1.9669x over previous
#include <cuda_runtime.h>
#include <cstdint>

// Problem constants
#define NN   100000
#define HID  128
#define RR   8
#define EE   75000

// Scratch (device globals — no allocation allowed)
__device__ float g_h [(size_t)NN * HID];               // relu(x@W_in + b_in)
__device__ float g_h2[(size_t)NN * HID];               // pre-relu layer-2 accumulator
__device__ float g_hr[(size_t)NN * RR * HID];          // hr[n][r][:] = h[n] @ W_rel[r]

// ---------------------------------------------------------------------------
// 128x128x128 fp32 GEMM tile, double-buffered smem, 256 threads, 8x8 microtile
// (quadrant layout: rows {ty*4, 64+ty*4}, cols {tx*4, 64+tx*4}).
//   C[m,:] = act( bias + A[m,0:128] @ B[0:128,0:128] ),  A ld = 128, C ld = ldc
// ---------------------------------------------------------------------------
template <bool RELU_A, bool HAS_BIAS, bool RELU_C>
__device__ __forceinline__ void gemm128_tile(
    const float* __restrict__ A, const float* __restrict__ B,
    const float* __restrict__ bias, float* __restrict__ C,
    int ldc, int block_row, int M,
    float (&As)[2][16][132], float (&Bs)[2][16][132])
{
    const int tid = threadIdx.x;
    const int tx = tid & 15;
    const int ty = tid >> 4;

    // load coordinates (512 float4 per tile, 2 per thread)
    const int a_row0 = tid >> 2;          // 0..63 (l=0), +64 for l=1
    const int a_k4   = (tid & 3) * 4;     // 0,4,8,12
    const int b_kr0  = tid >> 5;          // 0..7 (l=0), +8 for l=1
    const int b_c4   = (tid & 31) * 4;    // 0..124

    float4 ar[2], br[2];

    auto load_regs = [&](int k0) {
#pragma unroll
        for (int l = 0; l < 2; l++) {
            int row  = a_row0 + l * 64;
            int grow = block_row + row;
            float4 v = make_float4(0.f, 0.f, 0.f, 0.f);
            if (grow < M) {
                v = *reinterpret_cast<const float4*>(&A[(size_t)grow * 128 + k0 + a_k4]);
                if (RELU_A) {
                    v.x = fmaxf(v.x, 0.f); v.y = fmaxf(v.y, 0.f);
                    v.z = fmaxf(v.z, 0.f); v.w = fmaxf(v.w, 0.f);
                }
            }
            ar[l] = v;
            int kr = b_kr0 + l * 8;
            br[l] = *reinterpret_cast<const float4*>(&B[(size_t)(k0 + kr) * 128 + b_c4]);
        }
    };
    auto store_smem = [&](int st) {
#pragma unroll
        for (int l = 0; l < 2; l++) {
            int row = a_row0 + l * 64;
            As[st][a_k4 + 0][row] = ar[l].x;
            As[st][a_k4 + 1][row] = ar[l].y;
            As[st][a_k4 + 2][row] = ar[l].z;
            As[st][a_k4 + 3][row] = ar[l].w;
            int kr = b_kr0 + l * 8;
            *reinterpret_cast<float4*>(&Bs[st][kr][b_c4]) = br[l];
        }
    };

    float acc[8][8];
#pragma unroll
    for (int i = 0; i < 8; i++)
#pragma unroll
        for (int j = 0; j < 8; j++) acc[i][j] = 0.f;

    load_regs(0);
    store_smem(0);
    __syncthreads();

#pragma unroll
    for (int t = 0; t < 8; t++) {
        if (t < 7) load_regs((t + 1) * 16);   // prefetch next tile into regs
        const int cur = t & 1;
#pragma unroll
        for (int kk = 0; kk < 16; kk++) {
            float4 a0 = *reinterpret_cast<const float4*>(&As[cur][kk][ty * 4]);
            float4 a1 = *reinterpret_cast<const float4*>(&As[cur][kk][64 + ty * 4]);
            float4 b0 = *reinterpret_cast<const float4*>(&Bs[cur][kk][tx * 4]);
            float4 b1 = *reinterpret_cast<const float4*>(&Bs[cur][kk][64 + tx * 4]);
            float a[8] = {a0.x, a0.y, a0.z, a0.w, a1.x, a1.y, a1.z, a1.w};
            float b[8] = {b0.x, b0.y, b0.z, b0.w, b1.x, b1.y, b1.z, b1.w};
#pragma unroll
            for (int i = 0; i < 8; i++)
#pragma unroll
                for (int j = 0; j < 8; j++)
                    acc[i][j] = fmaf(a[i], b[j], acc[i][j]);
        }
        if (t < 7) {
            store_smem((t + 1) & 1);   // writes other buffer: safe, readers use cur
            __syncthreads();
        }
    }

    // Epilogue
    float bl[8] = {0.f, 0.f, 0.f, 0.f, 0.f, 0.f, 0.f, 0.f};
    if (HAS_BIAS) {
        float4 t0 = *reinterpret_cast<const float4*>(&bias[tx * 4]);
        float4 t1 = *reinterpret_cast<const float4*>(&bias[64 + tx * 4]);
        bl[0] = t0.x; bl[1] = t0.y; bl[2] = t0.z; bl[3] = t0.w;
        bl[4] = t1.x; bl[5] = t1.y; bl[6] = t1.z; bl[7] = t1.w;
    }
#pragma unroll
    for (int i = 0; i < 8; i++) {
        int grow = block_row + ((i < 4) ? (ty * 4 + i) : (64 + ty * 4 + (i - 4)));
        if (grow >= M) continue;
#pragma unroll
        for (int jh = 0; jh < 2; jh++) {
            int col = jh ? (64 + tx * 4) : (tx * 4);
            float4 v;
            v.x = acc[i][jh * 4 + 0] + bl[jh * 4 + 0];
            v.y = acc[i][jh * 4 + 1] + bl[jh * 4 + 1];
            v.z = acc[i][jh * 4 + 2] + bl[jh * 4 + 2];
            v.w = acc[i][jh * 4 + 3] + bl[jh * 4 + 3];
            if (RELU_C) {
                v.x = fmaxf(v.x, 0.f); v.y = fmaxf(v.y, 0.f);
                v.z = fmaxf(v.z, 0.f); v.w = fmaxf(v.w, 0.f);
            }
            *reinterpret_cast<float4*>(&C[(size_t)grow * ldc + col]) = v;
        }
    }
}

template <bool RELU_A, bool RELU_C>
__global__ void __launch_bounds__(256, 2)
gemm128(const float* __restrict__ A, const float* __restrict__ B,
        const float* __restrict__ bias, float* __restrict__ C, int M)
{
    __shared__ float As[2][16][132];
    __shared__ float Bs[2][16][132];
    gemm128_tile<RELU_A, true, RELU_C>(A, B, bias, C, 128, blockIdx.x * 128, M, As, Bs);
}

// Layer 2: y==0 -> h2 = h@W_self + b_self (pre-relu); y=1..8 -> hr slice r = h@W_rel[r]
__global__ void __launch_bounds__(256, 2)
gemm_layer2(const float* __restrict__ h, const float* __restrict__ W_self,
            const float* __restrict__ W_rel, const float* __restrict__ b_self,
            float* __restrict__ h2, float* __restrict__ hr, int M)
{
    __shared__ float As[2][16][132];
    __shared__ float Bs[2][16][132];
    int rel = blockIdx.y;
    if (rel == 0) {
        gemm128_tile<false, true, false>(h, W_self, b_self, h2, 128,
                                         blockIdx.x * 128, M, As, Bs);
    } else {
        gemm128_tile<false, false, false>(h, W_rel + (size_t)(rel - 1) * HID * HID,
                                          nullptr, hr + (size_t)(rel - 1) * HID,
                                          RR * HID, blockIdx.x * 128, M, As, Bs);
    }
}

// ---------------------------------------------------------------------------
// Edge scatter: h2[dst] += w * hr[src][r]
// 1 warp/edge; 4 scalar atomicAdds per lane (proven REDG path, L2-resident h2)
// ---------------------------------------------------------------------------
__global__ void __launch_bounds__(256)
scatter_kernel(const float* __restrict__ hr, const int* __restrict__ src,
               const int* __restrict__ dst, const float* __restrict__ w,
               float* __restrict__ h2)
{
    int e = (int)((blockIdx.x * blockDim.x + threadIdx.x) >> 5);
    if (e >= RR * EE) return;
    int lane = threadIdx.x & 31;

    int s = 0, d = 0; float wt = 0.f;
    if (lane == 0) { s = src[e]; d = dst[e]; wt = w[e]; }
    s  = __shfl_sync(0xffffffffu, s, 0);
    d  = __shfl_sync(0xffffffffu, d, 0);
    wt = __shfl_sync(0xffffffffu, wt, 0);
    int r = e / EE;

    float4 v = reinterpret_cast<const float4*>(hr + (size_t)s * (RR * HID) + r * HID)[lane];

    float* p = h2 + (size_t)d * HID + lane * 4;
    atomicAdd(p + 0, v.x * wt);
    atomicAdd(p + 1, v.y * wt);
    atomicAdd(p + 2, v.z * wt);
    atomicAdd(p + 3, v.w * wt);
}

// ---------------------------------------------------------------------------
// Launch
// ---------------------------------------------------------------------------
static float* sym_addr(const void* sym)
{
    void* p = nullptr;
    cudaGetSymbolAddress(&p, sym);
    return reinterpret_cast<float*>(p);
}

extern "C" void kernel_launch(void* const* d_in, const int* in_sizes, int n_in,
                              void* d_out, int out_size)
{
    // metadata order: x, edge_src, edge_dst, edge_w, W_in, b_in, W_rel,
    //                 W_self, b_self, W_out, b_out
    const float* x        = (const float*)d_in[0];
    const int*   edge_src = (const int*)  d_in[1];
    const int*   edge_dst = (const int*)  d_in[2];
    const float* edge_w   = (const float*)d_in[3];
    const float* W_in     = (const float*)d_in[4];
    const float* b_in     = (const float*)d_in[5];
    const float* W_rel    = (const float*)d_in[6];
    const float* W_self   = (const float*)d_in[7];
    const float* b_self   = (const float*)d_in[8];
    const float* W_out    = (const float*)d_in[9];
    const float* b_out    = (const float*)d_in[10];
    float* out = (float*)d_out;

    float* h  = sym_addr(g_h);
    float* h2 = sym_addr(g_h2);
    float* hr = sym_addr(g_hr);

    const int gemm_grid = (NN + 127) / 128;   // 782

    // Layer 1: h = relu(x @ W_in + b_in)
    gemm128<false, true><<<gemm_grid, 256>>>(x, W_in, b_in, h, NN);

    // Layer 2 GEMMs: h2 = h@W_self + b_self (pre-relu), hr[:,r,:] = h@W_rel[r]
    gemm_layer2<<<dim3(gemm_grid, RR + 1), 256>>>(h, W_self, W_rel, b_self, h2, hr, NN);

    // Scatter: h2[dst] += w * hr[src][r]   (h2 is 51MB -> L2-resident atomics)
    {
        int blocks = (RR * EE * 32 + 255) / 256;   // 75000
        scatter_kernel<<<blocks, 256>>>(hr, edge_src, edge_dst, edge_w, h2);
    }

    // Output: out = relu(h2) @ W_out + b_out   (relu fused into A-load)
    gemm128<true, false><<<gemm_grid, 256>>>(h2, W_out, b_out, out, NN);
}

// round 10
// speedup vs baseline: 3.5660x; 1.8130x over previous
#include <cuda_runtime.h>
#include <cuda_bf16.h>
#include <cstdint>

// Problem constants
#define NN   100000
#define HID  128
#define RR   8
#define EE   75000

// Scratch (device globals — no allocation allowed)
__device__ float g_h [(size_t)NN * HID];               // relu(x@W_in + b_in)
__device__ float g_h2[(size_t)NN * HID];               // pre-relu layer-2 accumulator
__device__ float g_hr[(size_t)NN * RR * HID];          // hr[n][r][:] = h[n] @ W_rel[r]

// ---------------------------------------------------------------------------
// Tensor-core GEMM: 128x128 block, K=128, bf16-split-3 (Ah*Bh + Ah*Bl + Al*Bh)
// 8 warps: warp_m = wid&3 (32 rows), warp_n = wid>>2 (64 cols).
// mma.sync.m16n8k16.f32.bf16 with fp32 accumulators.
// ---------------------------------------------------------------------------

// Padded smem: A rows 40 bf16 (80B: 8-row ldmatrix groups cover all 32 banks),
//              B rows 136 bf16 (272B: same property for ldmatrix.trans).
struct Smem {
    __nv_bfloat16 Ah[128][40];
    __nv_bfloat16 Al[128][40];
    __nv_bfloat16 Bh[32][136];
    __nv_bfloat16 Bl[32][136];
};

__device__ __forceinline__ uint32_t smem_u32(const void* p) {
    return (uint32_t)__cvta_generic_to_shared(p);
}

__device__ __forceinline__ void ldmat4(uint32_t* r, uint32_t a) {
    asm volatile("ldmatrix.sync.aligned.m8n8.x4.shared.b16 {%0,%1,%2,%3}, [%4];"
                 : "=r"(r[0]), "=r"(r[1]), "=r"(r[2]), "=r"(r[3]) : "r"(a));
}
__device__ __forceinline__ void ldmat4t(uint32_t* r, uint32_t a) {
    asm volatile("ldmatrix.sync.aligned.m8n8.x4.trans.shared.b16 {%0,%1,%2,%3}, [%4];"
                 : "=r"(r[0]), "=r"(r[1]), "=r"(r[2]), "=r"(r[3]) : "r"(a));
}
__device__ __forceinline__ void mma16816(float* d, const uint32_t* a,
                                         uint32_t b0, uint32_t b1) {
    asm volatile("mma.sync.aligned.m16n8k16.row.col.f32.bf16.bf16.f32 "
                 "{%0,%1,%2,%3}, {%4,%5,%6,%7}, {%8,%9}, {%0,%1,%2,%3};"
                 : "+f"(d[0]), "+f"(d[1]), "+f"(d[2]), "+f"(d[3])
                 : "r"(a[0]), "r"(a[1]), "r"(a[2]), "r"(a[3]), "r"(b0), "r"(b1));
}

__device__ __forceinline__ void split_bf16(float v, __nv_bfloat16& hi, __nv_bfloat16& lo) {
    hi = __float2bfloat16(v);
    lo = __float2bfloat16(v - __bfloat162float(hi));
}

template <bool RELU_A, bool HAS_BIAS, bool RELU_C>
__device__ __forceinline__ void gemm_mma_tile(
    const float* __restrict__ A, const float* __restrict__ B,
    const float* __restrict__ bias, float* __restrict__ C,
    int ldc, int block_row, int M, Smem& sm)
{
    const int tid  = threadIdx.x;
    const int lane = tid & 31;
    const int wid  = tid >> 5;
    const int warp_m = wid & 3;    // 0..3 -> 32-row slice
    const int warp_n = wid >> 2;   // 0..1 -> 64-col slice

    float acc[2][8][4];
#pragma unroll
    for (int mi = 0; mi < 2; mi++)
#pragma unroll
        for (int nj = 0; nj < 8; nj++)
#pragma unroll
            for (int q = 0; q < 4; q++) acc[mi][nj][q] = 0.f;

    // loader coords (256 threads, 16 fp32 each per 128x32 tile)
    const int a_row = tid >> 1;            // 0..127
    const int a_cb  = (tid & 1) * 16;      // 0 or 16
    const int b_row = tid >> 3;            // 0..31
    const int b_cb  = (tid & 7) * 16;      // 0..112

#pragma unroll 1
    for (int ck = 0; ck < 4; ck++) {
        const int k0 = ck * 32;

        // --- fill A planes (hi/lo), with optional ReLU and row guard ---
        {
            const int grow = block_row + a_row;
            const float* src = A + (size_t)grow * 128 + k0 + a_cb;
#pragma unroll
            for (int q = 0; q < 4; q++) {
                float4 v = make_float4(0.f, 0.f, 0.f, 0.f);
                if (grow < M) v = *reinterpret_cast<const float4*>(src + 4 * q);
                if (RELU_A) {
                    v.x = fmaxf(v.x, 0.f); v.y = fmaxf(v.y, 0.f);
                    v.z = fmaxf(v.z, 0.f); v.w = fmaxf(v.w, 0.f);
                }
                __nv_bfloat16 h0, h1, h2b, h3, l0, l1, l2, l3;
                split_bf16(v.x, h0, l0); split_bf16(v.y, h1, l1);
                split_bf16(v.z, h2b, l2); split_bf16(v.w, h3, l3);
                __nv_bfloat162* ph = reinterpret_cast<__nv_bfloat162*>(&sm.Ah[a_row][a_cb + 4 * q]);
                ph[0] = __nv_bfloat162(h0, h1); ph[1] = __nv_bfloat162(h2b, h3);
                __nv_bfloat162* pl = reinterpret_cast<__nv_bfloat162*>(&sm.Al[a_row][a_cb + 4 * q]);
                pl[0] = __nv_bfloat162(l0, l1); pl[1] = __nv_bfloat162(l2, l3);
            }
        }
        // --- fill B planes (hi/lo) ---
        {
            const float* src = B + (size_t)(k0 + b_row) * 128 + b_cb;
#pragma unroll
            for (int q = 0; q < 4; q++) {
                float4 v = *reinterpret_cast<const float4*>(src + 4 * q);
                __nv_bfloat16 h0, h1, h2b, h3, l0, l1, l2, l3;
                split_bf16(v.x, h0, l0); split_bf16(v.y, h1, l1);
                split_bf16(v.z, h2b, l2); split_bf16(v.w, h3, l3);
                __nv_bfloat162* ph = reinterpret_cast<__nv_bfloat162*>(&sm.Bh[b_row][b_cb + 4 * q]);
                ph[0] = __nv_bfloat162(h0, h1); ph[1] = __nv_bfloat162(h2b, h3);
                __nv_bfloat162* pl = reinterpret_cast<__nv_bfloat162*>(&sm.Bl[b_row][b_cb + 4 * q]);
                pl[0] = __nv_bfloat162(l0, l1); pl[1] = __nv_bfloat162(l2, l3);
            }
        }
        __syncthreads();

        // --- tensor-core work: 2 k16 steps, 3 split-products each ---
#pragma unroll
        for (int k16 = 0; k16 < 32; k16 += 16) {
            uint32_t ah[2][4], al[2][4];
#pragma unroll
            for (int mi = 0; mi < 2; mi++) {
                const int r = warp_m * 32 + mi * 16 + (lane & 15);
                const int c = k16 + (lane >> 4) * 8;
                ldmat4(ah[mi], smem_u32(&sm.Ah[r][c]));
                ldmat4(al[mi], smem_u32(&sm.Al[r][c]));
            }
#pragma unroll
            for (int j2 = 0; j2 < 4; j2++) {
                uint32_t bh[4], bl[4];
                const int br_ = k16 + (lane & 15);
                const int bc  = warp_n * 64 + j2 * 16 + (lane >> 4) * 8;
                ldmat4t(bh, smem_u32(&sm.Bh[br_][bc]));
                ldmat4t(bl, smem_u32(&sm.Bl[br_][bc]));
#pragma unroll
                for (int mi = 0; mi < 2; mi++) {
#pragma unroll
                    for (int hh = 0; hh < 2; hh++) {
                        float* d = acc[mi][j2 * 2 + hh];
                        mma16816(d, ah[mi], bh[2 * hh], bh[2 * hh + 1]);
                        mma16816(d, ah[mi], bl[2 * hh], bl[2 * hh + 1]);
                        mma16816(d, al[mi], bh[2 * hh], bh[2 * hh + 1]);
                    }
                }
            }
        }
        __syncthreads();
    }

    // --- epilogue: bias (+ReLU), float2 stores per acc fragment ---
    const int qrow = lane >> 2;
    const int qcol = (lane & 3) * 2;
#pragma unroll
    for (int mi = 0; mi < 2; mi++) {
#pragma unroll
        for (int nj = 0; nj < 8; nj++) {
            const int col = warp_n * 64 + nj * 8 + qcol;
            float bx = 0.f, by = 0.f;
            if (HAS_BIAS) {
                float2 b2 = *reinterpret_cast<const float2*>(&bias[col]);
                bx = b2.x; by = b2.y;
            }
            const float* d = acc[mi][nj];
            const int r0 = block_row + warp_m * 32 + mi * 16 + qrow;
            if (r0 < M) {
                float2 o = make_float2(d[0] + bx, d[1] + by);
                if (RELU_C) { o.x = fmaxf(o.x, 0.f); o.y = fmaxf(o.y, 0.f); }
                *reinterpret_cast<float2*>(&C[(size_t)r0 * ldc + col]) = o;
            }
            const int r1 = r0 + 8;
            if (r1 < M) {
                float2 o = make_float2(d[2] + bx, d[3] + by);
                if (RELU_C) { o.x = fmaxf(o.x, 0.f); o.y = fmaxf(o.y, 0.f); }
                *reinterpret_cast<float2*>(&C[(size_t)r1 * ldc + col]) = o;
            }
        }
    }
}

template <bool RELU_A, bool RELU_C>
__global__ void __launch_bounds__(256, 2)
gemm_mma(const float* __restrict__ A, const float* __restrict__ B,
         const float* __restrict__ bias, float* __restrict__ C, int M)
{
    __shared__ Smem sm;
    gemm_mma_tile<RELU_A, true, RELU_C>(A, B, bias, C, 128, blockIdx.x * 128, M, sm);
}

// Layer 2: y==0 -> h2 = h@W_self + b_self (pre-relu); y=1..8 -> hr slice r = h@W_rel[r]
__global__ void __launch_bounds__(256, 2)
gemm_layer2_mma(const float* __restrict__ h, const float* __restrict__ W_self,
                const float* __restrict__ W_rel, const float* __restrict__ b_self,
                float* __restrict__ h2, float* __restrict__ hr, int M)
{
    __shared__ Smem sm;
    const int rel = blockIdx.y;
    if (rel == 0) {
        gemm_mma_tile<false, true, false>(h, W_self, b_self, h2, 128,
                                          blockIdx.x * 128, M, sm);
    } else {
        gemm_mma_tile<false, false, false>(h, W_rel + (size_t)(rel - 1) * HID * HID,
                                           nullptr, hr + (size_t)(rel - 1) * HID,
                                           RR * HID, blockIdx.x * 128, M, sm);
    }
}

// ---------------------------------------------------------------------------
// Edge scatter: h2[dst] += w * hr[src][r]
// 1 warp/edge; 4 scalar atomicAdds per lane (proven REDG path, L2-resident h2)
// ---------------------------------------------------------------------------
__global__ void __launch_bounds__(256)
scatter_kernel(const float* __restrict__ hr, const int* __restrict__ src,
               const int* __restrict__ dst, const float* __restrict__ w,
               float* __restrict__ h2)
{
    int e = (int)((blockIdx.x * blockDim.x + threadIdx.x) >> 5);
    if (e >= RR * EE) return;
    int lane = threadIdx.x & 31;

    int s = 0, d = 0; float wt = 0.f;
    if (lane == 0) { s = src[e]; d = dst[e]; wt = w[e]; }
    s  = __shfl_sync(0xffffffffu, s, 0);
    d  = __shfl_sync(0xffffffffu, d, 0);
    wt = __shfl_sync(0xffffffffu, wt, 0);
    int r = e / EE;

    float4 v = reinterpret_cast<const float4*>(hr + (size_t)s * (RR * HID) + r * HID)[lane];

    float* p = h2 + (size_t)d * HID + lane * 4;
    atomicAdd(p + 0, v.x * wt);
    atomicAdd(p + 1, v.y * wt);
    atomicAdd(p + 2, v.z * wt);
    atomicAdd(p + 3, v.w * wt);
}

// ---------------------------------------------------------------------------
// Launch
// ---------------------------------------------------------------------------
static float* sym_addr(const void* sym)
{
    void* p = nullptr;
    cudaGetSymbolAddress(&p, sym);
    return reinterpret_cast<float*>(p);
}

extern "C" void kernel_launch(void* const* d_in, const int* in_sizes, int n_in,
                              void* d_out, int out_size)
{
    // metadata order: x, edge_src, edge_dst, edge_w, W_in, b_in, W_rel,
    //                 W_self, b_self, W_out, b_out
    const float* x        = (const float*)d_in[0];
    const int*   edge_src = (const int*)  d_in[1];
    const int*   edge_dst = (const int*)  d_in[2];
    const float* edge_w   = (const float*)d_in[3];
    const float* W_in     = (const float*)d_in[4];
    const float* b_in     = (const float*)d_in[5];
    const float* W_rel    = (const float*)d_in[6];
    const float* W_self   = (const float*)d_in[7];
    const float* b_self   = (const float*)d_in[8];
    const float* W_out    = (const float*)d_in[9];
    const float* b_out    = (const float*)d_in[10];
    float* out = (float*)d_out;

    float* h  = sym_addr(g_h);
    float* h2 = sym_addr(g_h2);
    float* hr = sym_addr(g_hr);

    const int gemm_grid = (NN + 127) / 128;   // 782

    // Layer 1: h = relu(x @ W_in + b_in)
    gemm_mma<false, true><<<gemm_grid, 256>>>(x, W_in, b_in, h, NN);

    // Layer 2 GEMMs: h2 = h@W_self + b_self (pre-relu), hr[:,r,:] = h@W_rel[r]
    gemm_layer2_mma<<<dim3(gemm_grid, RR + 1), 256>>>(h, W_self, W_rel, b_self, h2, hr, NN);

    // Scatter: h2[dst] += w * hr[src][r]   (h2 is 51MB -> L2-resident atomics)
    {
        int blocks = (RR * EE * 32 + 255) / 256;   // 75000
        scatter_kernel<<<blocks, 256>>>(hr, edge_src, edge_dst, edge_w, h2);
    }

    // Output: out = relu(h2) @ W_out + b_out   (relu fused into A-load)
    gemm_mma<true, false><<<gemm_grid, 256>>>(h2, W_out, b_out, out, NN);
}

// round 12
// speedup vs baseline: 3.7555x; 1.0531x over previous
#include <cuda_runtime.h>
#include <cuda_bf16.h>
#include <cstdint>

// Problem constants
#define NN   100000
#define HID  128
#define RR   8
#define EE   75000

// Scratch (device globals — no allocation allowed)
__device__ __nv_bfloat16 g_xh [(size_t)NN * HID];      // x hi/lo planes
__device__ __nv_bfloat16 g_xl [(size_t)NN * HID];
__device__ __nv_bfloat16 g_hh [(size_t)NN * HID];      // h = relu(x@W_in+b_in) planes
__device__ __nv_bfloat16 g_hl [(size_t)NN * HID];
__device__ float         g_h2 [(size_t)NN * HID];      // pre-relu layer-2 accumulator (fp32, atomics)
__device__ __nv_bfloat16 g_h2h[(size_t)NN * HID];      // relu(h2) planes
__device__ __nv_bfloat16 g_h2l[(size_t)NN * HID];
__device__ float         g_hr [(size_t)NN * RR * HID]; // hr[n][r][:] = h[n]@W_rel[r]
// Weight planes: idx 0=W_in, 1=W_self, 2..9=W_rel[r], 10=W_out (each 128x128)
__device__ __nv_bfloat16 g_wh [(size_t)11 * HID * HID];
__device__ __nv_bfloat16 g_wl [(size_t)11 * HID * HID];

__device__ __forceinline__ void split_bf16(float v, __nv_bfloat16& hi, __nv_bfloat16& lo) {
    hi = __float2bfloat16(v);
    lo = __float2bfloat16(v - __bfloat162float(hi));
}

// ---------------------------------------------------------------------------
// fp32 -> (hi, lo) bf16 planes, optional ReLU. n4 = element count / 4.
// ---------------------------------------------------------------------------
__global__ void convert_planes(const float* __restrict__ s,
                               __nv_bfloat16* __restrict__ hi,
                               __nv_bfloat16* __restrict__ lo,
                               size_t n4, int relu)
{
    const float4* s4 = reinterpret_cast<const float4*>(s);
    __nv_bfloat162* h2p = reinterpret_cast<__nv_bfloat162*>(hi);
    __nv_bfloat162* l2p = reinterpret_cast<__nv_bfloat162*>(lo);
    for (size_t i = (size_t)blockIdx.x * blockDim.x + threadIdx.x;
         i < n4; i += (size_t)gridDim.x * blockDim.x) {
        float4 v = s4[i];
        if (relu) {
            v.x = fmaxf(v.x, 0.f); v.y = fmaxf(v.y, 0.f);
            v.z = fmaxf(v.z, 0.f); v.w = fmaxf(v.w, 0.f);
        }
        __nv_bfloat16 h0, h1, h2b, h3, l0, l1, l2, l3;
        split_bf16(v.x, h0, l0); split_bf16(v.y, h1, l1);
        split_bf16(v.z, h2b, l2); split_bf16(v.w, h3, l3);
        h2p[i * 2]     = __nv_bfloat162(h0, h1);
        h2p[i * 2 + 1] = __nv_bfloat162(h2b, h3);
        l2p[i * 2]     = __nv_bfloat162(l0, l1);
        l2p[i * 2 + 1] = __nv_bfloat162(l2, l3);
    }
}

// ---------------------------------------------------------------------------
// Tensor-core GEMM on precomputed bf16 planes. 128x128 block, K=128.
// bf16-split-3: C = Ah*Bh + Ah*Bl + Al*Bh (fp32 accum).
// 8 warps: warp_m = wid&3 (32 rows), warp_n = wid>>2 (64 cols).
// ---------------------------------------------------------------------------
struct Smem {
    __nv_bfloat16 Ah[128][40];   // 80B rows: 8-row ldmatrix groups cover 32 banks
    __nv_bfloat16 Al[128][40];
    __nv_bfloat16 Bh[32][136];   // 272B rows: same for ldmatrix.trans
    __nv_bfloat16 Bl[32][136];
};

__device__ __forceinline__ uint32_t smem_u32(const void* p) {
    return (uint32_t)__cvta_generic_to_shared(p);
}
__device__ __forceinline__ void ldmat4(uint32_t* r, uint32_t a) {
    asm volatile("ldmatrix.sync.aligned.m8n8.x4.shared.b16 {%0,%1,%2,%3}, [%4];"
                 : "=r"(r[0]), "=r"(r[1]), "=r"(r[2]), "=r"(r[3]) : "r"(a));
}
__device__ __forceinline__ void ldmat4t(uint32_t* r, uint32_t a) {
    asm volatile("ldmatrix.sync.aligned.m8n8.x4.trans.shared.b16 {%0,%1,%2,%3}, [%4];"
                 : "=r"(r[0]), "=r"(r[1]), "=r"(r[2]), "=r"(r[3]) : "r"(a));
}
__device__ __forceinline__ void mma16816(float* d, const uint32_t* a,
                                         uint32_t b0, uint32_t b1) {
    asm volatile("mma.sync.aligned.m16n8k16.row.col.f32.bf16.bf16.f32 "
                 "{%0,%1,%2,%3}, {%4,%5,%6,%7}, {%8,%9}, {%0,%1,%2,%3};"
                 : "+f"(d[0]), "+f"(d[1]), "+f"(d[2]), "+f"(d[3])
                 : "r"(a[0]), "r"(a[1]), "r"(a[2]), "r"(a[3]), "r"(b0), "r"(b1));
}

template <bool HAS_BIAS, bool RELU_C, bool OUT_PLANES>
__device__ __forceinline__ void gemm_tile_p(
    const __nv_bfloat16* __restrict__ Ah_g, const __nv_bfloat16* __restrict__ Al_g,
    const __nv_bfloat16* __restrict__ Bh_g, const __nv_bfloat16* __restrict__ Bl_g,
    const float* __restrict__ bias,
    float* __restrict__ Cf, __nv_bfloat16* __restrict__ Ch, __nv_bfloat16* __restrict__ Cl,
    int ldc, int block_row, int M, Smem& sm)
{
    const int tid  = threadIdx.x;
    const int lane = tid & 31;
    const int wid  = tid >> 5;
    const int warp_m = wid & 3;
    const int warp_n = wid >> 2;

    float acc[2][8][4];
#pragma unroll
    for (int mi = 0; mi < 2; mi++)
#pragma unroll
        for (int nj = 0; nj < 8; nj++)
#pragma unroll
            for (int q = 0; q < 4; q++) acc[mi][nj][q] = 0.f;

#pragma unroll 1
    for (int ck = 0; ck < 4; ck++) {
        const int k0 = ck * 32;

        // --- load A planes (bf16 copy, no math) ---
#pragma unroll
        for (int l = 0; l < 2; l++) {
            const int idx = tid + 256 * l;       // 0..511
            const int row = idx >> 2;            // 0..127
            const int c8  = (idx & 3) * 8;       // 0,8,16,24
            const int grow = block_row + row;
            uint4 vh = make_uint4(0, 0, 0, 0), vl = make_uint4(0, 0, 0, 0);
            if (grow < M) {
                vh = *reinterpret_cast<const uint4*>(Ah_g + (size_t)grow * 128 + k0 + c8);
                vl = *reinterpret_cast<const uint4*>(Al_g + (size_t)grow * 128 + k0 + c8);
            }
            *reinterpret_cast<uint4*>(&sm.Ah[row][c8]) = vh;
            *reinterpret_cast<uint4*>(&sm.Al[row][c8]) = vl;
        }
        // --- load B planes ---
#pragma unroll
        for (int l = 0; l < 2; l++) {
            const int idx = tid + 256 * l;       // 0..511
            const int row = idx >> 4;            // 0..31
            const int c8  = (idx & 15) * 8;      // 0..120
            *reinterpret_cast<uint4*>(&sm.Bh[row][c8]) =
                *reinterpret_cast<const uint4*>(Bh_g + (size_t)(k0 + row) * 128 + c8);
            *reinterpret_cast<uint4*>(&sm.Bl[row][c8]) =
                *reinterpret_cast<const uint4*>(Bl_g + (size_t)(k0 + row) * 128 + c8);
        }
        __syncthreads();

        // --- tensor-core work: 2 k16 steps, 3 split-products each ---
#pragma unroll
        for (int k16 = 0; k16 < 32; k16 += 16) {
            uint32_t ah[2][4], al[2][4];
#pragma unroll
            for (int mi = 0; mi < 2; mi++) {
                const int r = warp_m * 32 + mi * 16 + (lane & 15);
                const int c = k16 + (lane >> 4) * 8;
                ldmat4(ah[mi], smem_u32(&sm.Ah[r][c]));
                ldmat4(al[mi], smem_u32(&sm.Al[r][c]));
            }
#pragma unroll
            for (int j2 = 0; j2 < 4; j2++) {
                uint32_t bh[4], bl[4];
                const int br_ = k16 + (lane & 15);
                const int bc  = warp_n * 64 + j2 * 16 + (lane >> 4) * 8;
                ldmat4t(bh, smem_u32(&sm.Bh[br_][bc]));
                ldmat4t(bl, smem_u32(&sm.Bl[br_][bc]));
#pragma unroll
                for (int mi = 0; mi < 2; mi++) {
#pragma unroll
                    for (int hh = 0; hh < 2; hh++) {
                        float* d = acc[mi][j2 * 2 + hh];
                        mma16816(d, ah[mi], bh[2 * hh], bh[2 * hh + 1]);
                        mma16816(d, ah[mi], bl[2 * hh], bl[2 * hh + 1]);
                        mma16816(d, al[mi], bh[2 * hh], bh[2 * hh + 1]);
                    }
                }
            }
        }
        __syncthreads();
    }

    // --- epilogue ---
    const int qrow = lane >> 2;
    const int qcol = (lane & 3) * 2;
#pragma unroll
    for (int mi = 0; mi < 2; mi++) {
#pragma unroll
        for (int nj = 0; nj < 8; nj++) {
            const int col = warp_n * 64 + nj * 8 + qcol;
            float bx = 0.f, by = 0.f;
            if (HAS_BIAS) {
                float2 b2 = *reinterpret_cast<const float2*>(&bias[col]);
                bx = b2.x; by = b2.y;
            }
            const float* d = acc[mi][nj];
#pragma unroll
            for (int half = 0; half < 2; half++) {
                const int r = block_row + warp_m * 32 + mi * 16 + qrow + half * 8;
                if (r >= M) continue;
                float vx = d[half * 2 + 0] + bx;
                float vy = d[half * 2 + 1] + by;
                if (RELU_C) { vx = fmaxf(vx, 0.f); vy = fmaxf(vy, 0.f); }
                if (OUT_PLANES) {
                    __nv_bfloat16 hx, lx, hy, ly;
                    split_bf16(vx, hx, lx); split_bf16(vy, hy, ly);
                    *reinterpret_cast<__nv_bfloat162*>(&Ch[(size_t)r * 128 + col]) =
                        __nv_bfloat162(hx, hy);
                    *reinterpret_cast<__nv_bfloat162*>(&Cl[(size_t)r * 128 + col]) =
                        __nv_bfloat162(lx, ly);
                } else {
                    *reinterpret_cast<float2*>(&Cf[(size_t)r * ldc + col]) =
                        make_float2(vx, vy);
                }
            }
        }
    }
}

// Layer 1: h planes = relu(x @ W_in + b_in)  (planes in, planes out)
__global__ void __launch_bounds__(256, 2)
gemm_layer1(const float* __restrict__ b_in, int M)
{
    __shared__ Smem sm;
    gemm_tile_p<true, true, true>(g_xh, g_xl, g_wh, g_wl, b_in,
                                  nullptr, g_hh, g_hl, 0, blockIdx.x * 128, M, sm);
}

// Layer 2: y==0 -> h2 = h@W_self + b_self (fp32, pre-relu); y=1..8 -> hr slice
__global__ void __launch_bounds__(256, 2)
gemm_layer2(const float* __restrict__ b_self, int M)
{
    __shared__ Smem sm;
    const int rel = blockIdx.y;
    if (rel == 0) {
        gemm_tile_p<true, false, false>(g_hh, g_hl,
                                        g_wh + (size_t)1 * HID * HID,
                                        g_wl + (size_t)1 * HID * HID,
                                        b_self, g_h2, nullptr, nullptr,
                                        128, blockIdx.x * 128, M, sm);
    } else {
        gemm_tile_p<false, false, false>(g_hh, g_hl,
                                         g_wh + (size_t)(rel + 1) * HID * HID,
                                         g_wl + (size_t)(rel + 1) * HID * HID,
                                         nullptr, g_hr + (size_t)(rel - 1) * HID,
                                         nullptr, nullptr,
                                         RR * HID, blockIdx.x * 128, M, sm);
    }
}

// Final: out = relu(h2) @ W_out + b_out  (relu already applied in h2 planes)
__global__ void __launch_bounds__(256, 2)
gemm_final(const float* __restrict__ b_out, float* __restrict__ out, int M)
{
    __shared__ Smem sm;
    gemm_tile_p<true, false, false>(g_h2h, g_h2l,
                                    g_wh + (size_t)10 * HID * HID,
                                    g_wl + (size_t)10 * HID * HID,
                                    b_out, out, nullptr, nullptr,
                                    128, blockIdx.x * 128, M, sm);
}

// ---------------------------------------------------------------------------
// Edge scatter: h2[dst] += w * hr[src][r]   (1 warp/edge, L2-resident atomics)
// ---------------------------------------------------------------------------
__global__ void __launch_bounds__(256)
scatter_kernel(const float* __restrict__ hr, const int* __restrict__ src,
               const int* __restrict__ dst, const float* __restrict__ w,
               float* __restrict__ h2)
{
    int e = (int)((blockIdx.x * blockDim.x + threadIdx.x) >> 5);
    if (e >= RR * EE) return;
    int lane = threadIdx.x & 31;

    int s = 0, d = 0; float wt = 0.f;
    if (lane == 0) { s = src[e]; d = dst[e]; wt = w[e]; }
    s  = __shfl_sync(0xffffffffu, s, 0);
    d  = __shfl_sync(0xffffffffu, d, 0);
    wt = __shfl_sync(0xffffffffu, wt, 0);
    int r = e / EE;

    float4 v = reinterpret_cast<const float4*>(hr + (size_t)s * (RR * HID) + r * HID)[lane];

    float* p = h2 + (size_t)d * HID + lane * 4;
    atomicAdd(p + 0, v.x * wt);
    atomicAdd(p + 1, v.y * wt);
    atomicAdd(p + 2, v.z * wt);
    atomicAdd(p + 3, v.w * wt);
}

// ---------------------------------------------------------------------------
// Launch
// ---------------------------------------------------------------------------
extern "C" void kernel_launch(void* const* d_in, const int* in_sizes, int n_in,
                              void* d_out, int out_size)
{
    // metadata order: x, edge_src, edge_dst, edge_w, W_in, b_in, W_rel,
    //                 W_self, b_self, W_out, b_out
    const float* x        = (const float*)d_in[0];
    const int*   edge_src = (const int*)  d_in[1];
    const int*   edge_dst = (const int*)  d_in[2];
    const float* edge_w   = (const float*)d_in[3];
    const float* W_in     = (const float*)d_in[4];
    const float* b_in     = (const float*)d_in[5];
    const float* W_rel    = (const float*)d_in[6];
    const float* W_self   = (const float*)d_in[7];
    const float* b_self   = (const float*)d_in[8];
    const float* W_out    = (const float*)d_in[9];
    const float* b_out    = (const float*)d_in[10];
    float* out = (float*)d_out;

    __nv_bfloat16* wh = nullptr; __nv_bfloat16* wl = nullptr;
    {
        void* p = nullptr;
        cudaGetSymbolAddress(&p, g_wh); wh = (__nv_bfloat16*)p;
        cudaGetSymbolAddress(&p, g_wl); wl = (__nv_bfloat16*)p;
    }
    __nv_bfloat16 *xh, *xl, *h2h, *h2l;
    float *h2, *hr;
    {
        void* p = nullptr;
        cudaGetSymbolAddress(&p, g_xh);  xh  = (__nv_bfloat16*)p;
        cudaGetSymbolAddress(&p, g_xl);  xl  = (__nv_bfloat16*)p;
        cudaGetSymbolAddress(&p, g_h2h); h2h = (__nv_bfloat16*)p;
        cudaGetSymbolAddress(&p, g_h2l); h2l = (__nv_bfloat16*)p;
        cudaGetSymbolAddress(&p, g_h2);  h2  = (float*)p;
        cudaGetSymbolAddress(&p, g_hr);  hr  = (float*)p;
    }

    const size_t WSZ = (size_t)HID * HID;           // 16384
    const int gemm_grid = (NN + 127) / 128;         // 782

    // Precompute bf16 planes: x + all weights
    convert_planes<<<4096, 256>>>(x, xh, xl, (size_t)NN * HID / 4, 0);
    convert_planes<<<32, 256>>>(W_in,   wh,             wl,             WSZ / 4, 0);
    convert_planes<<<32, 256>>>(W_self, wh + WSZ,       wl + WSZ,       WSZ / 4, 0);
    convert_planes<<<128, 256>>>(W_rel, wh + 2 * WSZ,   wl + 2 * WSZ,   RR * WSZ / 4, 0);
    convert_planes<<<32, 256>>>(W_out,  wh + 10 * WSZ,  wl + 10 * WSZ,  WSZ / 4, 0);

    // Layer 1: h planes = relu(x @ W_in + b_in)
    gemm_layer1<<<gemm_grid, 256>>>(b_in, NN);

    // Layer 2: h2 = h@W_self + b_self (fp32), hr[:,r,:] = h@W_rel[r]
    gemm_layer2<<<dim3(gemm_grid, RR + 1), 256>>>(b_self, NN);

    // Scatter: h2[dst] += w * hr[src][r]
    {
        int blocks = (RR * EE * 32 + 255) / 256;    // 75000
        scatter_kernel<<<blocks, 256>>>(hr, edge_src, edge_dst, edge_w, h2);
    }

    // relu(h2) -> planes
    convert_planes<<<4096, 256>>>(h2, h2h, h2l, (size_t)NN * HID / 4, 1);

    // Output: out = relu(h2) @ W_out + b_out
    gemm_final<<<gemm_grid, 256>>>(b_out, out, NN);
}

// round 17
// speedup vs baseline: 4.0906x; 1.0892x over previous
#include <cuda_runtime.h>
#include <cuda_bf16.h>
#include <cstdint>

// Problem constants
#define NN   100000
#define HID  128
#define RR   8
#define EE   75000

// Scratch (device globals — no allocation allowed)
__device__ __nv_bfloat16 g_xh [(size_t)NN * HID];      // x hi/lo planes
__device__ __nv_bfloat16 g_xl [(size_t)NN * HID];
__device__ __nv_bfloat16 g_hh [(size_t)NN * HID];      // h = relu(x@W_in+b_in) planes
__device__ __nv_bfloat16 g_hl [(size_t)NN * HID];
__device__ float         g_h2 [(size_t)NN * HID];      // pre-relu layer-2 accumulator (fp32, atomics)
__device__ __nv_bfloat16 g_h2h[(size_t)NN * HID];      // relu(h2) planes
__device__ __nv_bfloat16 g_h2l[(size_t)NN * HID];
__device__ float         g_hr [(size_t)NN * RR * HID]; // hr[n][r][:] = h[n]@W_rel[r]
// Weight planes: idx 0=W_in, 1=W_self, 2..9=W_rel[r], 10=W_out (each 128x128)
__device__ __nv_bfloat16 g_wh [(size_t)11 * HID * HID];
__device__ __nv_bfloat16 g_wl [(size_t)11 * HID * HID];

__device__ __forceinline__ void split_bf16(float v, __nv_bfloat16& hi, __nv_bfloat16& lo) {
    hi = __float2bfloat16(v);
    lo = __float2bfloat16(v - __bfloat162float(hi));
}

// ---------------------------------------------------------------------------
// fp32 -> (hi, lo) bf16 planes, optional ReLU. n4 = element count / 4.
// ---------------------------------------------------------------------------
__global__ void convert_planes(const float* __restrict__ s,
                               __nv_bfloat16* __restrict__ hi,
                               __nv_bfloat16* __restrict__ lo,
                               size_t n4, int relu)
{
    const float4* s4 = reinterpret_cast<const float4*>(s);
    __nv_bfloat162* h2p = reinterpret_cast<__nv_bfloat162*>(hi);
    __nv_bfloat162* l2p = reinterpret_cast<__nv_bfloat162*>(lo);
    for (size_t i = (size_t)blockIdx.x * blockDim.x + threadIdx.x;
         i < n4; i += (size_t)gridDim.x * blockDim.x) {
        float4 v = s4[i];
        if (relu) {
            v.x = fmaxf(v.x, 0.f); v.y = fmaxf(v.y, 0.f);
            v.z = fmaxf(v.z, 0.f); v.w = fmaxf(v.w, 0.f);
        }
        __nv_bfloat16 h0, h1, h2b, h3, l0, l1, l2, l3;
        split_bf16(v.x, h0, l0); split_bf16(v.y, h1, l1);
        split_bf16(v.z, h2b, l2); split_bf16(v.w, h3, l3);
        h2p[i * 2]     = __nv_bfloat162(h0, h1);
        h2p[i * 2 + 1] = __nv_bfloat162(h2b, h3);
        l2p[i * 2]     = __nv_bfloat162(l0, l1);
        l2p[i * 2 + 1] = __nv_bfloat162(l2, l3);
    }
}

// ---------------------------------------------------------------------------
// Tensor-core GEMM, cp.async double-buffered. 128x128 block, K=128.
// bf16-split-3: C = Ah*Bh + Ah*Bl + Al*Bh (fp32 accum).
// 8 warps: warp_m = wid&3 (32 rows), warp_n = wid>>2 (64 cols).
// ---------------------------------------------------------------------------
struct Smem {
    __nv_bfloat16 Ah[128][40];   // 80B rows: 8-row ldmatrix groups cover 32 banks
    __nv_bfloat16 Al[128][40];
    __nv_bfloat16 Bh[32][136];   // 272B rows: same for ldmatrix.trans
    __nv_bfloat16 Bl[32][136];
};

__device__ __forceinline__ uint32_t smem_u32(const void* p) {
    return (uint32_t)__cvta_generic_to_shared(p);
}
__device__ __forceinline__ void cp16(uint32_t dst, const void* src, bool valid) {
    int sz = valid ? 16 : 0;
    asm volatile("cp.async.cg.shared.global [%0], [%1], 16, %2;"
                 :: "r"(dst), "l"(src), "r"(sz) : "memory");
}
__device__ __forceinline__ void cp_commit() {
    asm volatile("cp.async.commit_group;" ::: "memory");
}
__device__ __forceinline__ void ldmat4(uint32_t* r, uint32_t a) {
    asm volatile("ldmatrix.sync.aligned.m8n8.x4.shared.b16 {%0,%1,%2,%3}, [%4];"
                 : "=r"(r[0]), "=r"(r[1]), "=r"(r[2]), "=r"(r[3]) : "r"(a));
}
__device__ __forceinline__ void ldmat4t(uint32_t* r, uint32_t a) {
    asm volatile("ldmatrix.sync.aligned.m8n8.x4.trans.shared.b16 {%0,%1,%2,%3}, [%4];"
                 : "=r"(r[0]), "=r"(r[1]), "=r"(r[2]), "=r"(r[3]) : "r"(a));
}
__device__ __forceinline__ void mma16816(float* d, const uint32_t* a,
                                         uint32_t b0, uint32_t b1) {
    asm volatile("mma.sync.aligned.m16n8k16.row.col.f32.bf16.bf16.f32 "
                 "{%0,%1,%2,%3}, {%4,%5,%6,%7}, {%8,%9}, {%0,%1,%2,%3};"
                 : "+f"(d[0]), "+f"(d[1]), "+f"(d[2]), "+f"(d[3])
                 : "r"(a[0]), "r"(a[1]), "r"(a[2]), "r"(a[3]), "r"(b0), "r"(b1));
}

__device__ __forceinline__ void prefetch_chunk(
    Smem& sm,
    const __nv_bfloat16* __restrict__ Ah_g, const __nv_bfloat16* __restrict__ Al_g,
    const __nv_bfloat16* __restrict__ Bh_g, const __nv_bfloat16* __restrict__ Bl_g,
    int k0, int block_row, int M, int tid)
{
#pragma unroll
    for (int l = 0; l < 2; l++) {
        const int idx = tid + 256 * l;       // 0..511
        const int row = idx >> 2;            // 0..127
        const int c8  = (idx & 3) * 8;       // 0,8,16,24
        const int grow = block_row + row;
        const bool valid = grow < M;
        const int srow = valid ? grow : block_row;   // clamp to safe address
        cp16(smem_u32(&sm.Ah[row][c8]), Ah_g + (size_t)srow * 128 + k0 + c8, valid);
        cp16(smem_u32(&sm.Al[row][c8]), Al_g + (size_t)srow * 128 + k0 + c8, valid);
    }
#pragma unroll
    for (int l = 0; l < 2; l++) {
        const int idx = tid + 256 * l;       // 0..511
        const int row = idx >> 4;            // 0..31
        const int c8  = (idx & 15) * 8;      // 0..120
        cp16(smem_u32(&sm.Bh[row][c8]), Bh_g + (size_t)(k0 + row) * 128 + c8, true);
        cp16(smem_u32(&sm.Bl[row][c8]), Bl_g + (size_t)(k0 + row) * 128 + c8, true);
    }
}

template <bool HAS_BIAS, bool RELU_C, bool OUT_PLANES>
__device__ __forceinline__ void gemm_tile_p(
    const __nv_bfloat16* __restrict__ Ah_g, const __nv_bfloat16* __restrict__ Al_g,
    const __nv_bfloat16* __restrict__ Bh_g, const __nv_bfloat16* __restrict__ Bl_g,
    const float* __restrict__ bias,
    float* __restrict__ Cf, __nv_bfloat16* __restrict__ Ch, __nv_bfloat16* __restrict__ Cl,
    int ldc, int block_row, int M, Smem* bufs)
{
    const int tid  = threadIdx.x;
    const int lane = tid & 31;
    const int wid  = tid >> 5;
    const int warp_m = wid & 3;
    const int warp_n = wid >> 2;

    float acc[2][8][4];
#pragma unroll
    for (int mi = 0; mi < 2; mi++)
#pragma unroll
        for (int nj = 0; nj < 8; nj++)
#pragma unroll
            for (int q = 0; q < 4; q++) acc[mi][nj][q] = 0.f;

    // Prefetch chunks 0 and 1
    prefetch_chunk(bufs[0], Ah_g, Al_g, Bh_g, Bl_g, 0,  block_row, M, tid);
    cp_commit();
    prefetch_chunk(bufs[1], Ah_g, Al_g, Bh_g, Bl_g, 32, block_row, M, tid);
    cp_commit();

#pragma unroll
    for (int ck = 0; ck < 4; ck++) {
        if (ck < 3) asm volatile("cp.async.wait_group 1;" ::: "memory");
        else        asm volatile("cp.async.wait_group 0;" ::: "memory");
        __syncthreads();

        Smem& sm = bufs[ck & 1];
#pragma unroll
        for (int k16 = 0; k16 < 32; k16 += 16) {
            uint32_t ah[2][4], al[2][4];
#pragma unroll
            for (int mi = 0; mi < 2; mi++) {
                const int r = warp_m * 32 + mi * 16 + (lane & 15);
                const int c = k16 + (lane >> 4) * 8;
                ldmat4(ah[mi], smem_u32(&sm.Ah[r][c]));
                ldmat4(al[mi], smem_u32(&sm.Al[r][c]));
            }
#pragma unroll
            for (int j2 = 0; j2 < 4; j2++) {
                uint32_t bh[4], bl[4];
                const int br_ = k16 + (lane & 15);
                const int bc  = warp_n * 64 + j2 * 16 + (lane >> 4) * 8;
                ldmat4t(bh, smem_u32(&sm.Bh[br_][bc]));
                ldmat4t(bl, smem_u32(&sm.Bl[br_][bc]));
#pragma unroll
                for (int mi = 0; mi < 2; mi++) {
#pragma unroll
                    for (int hh = 0; hh < 2; hh++) {
                        float* d = acc[mi][j2 * 2 + hh];
                        mma16816(d, ah[mi], bh[2 * hh], bh[2 * hh + 1]);
                        mma16816(d, ah[mi], bl[2 * hh], bl[2 * hh + 1]);
                        mma16816(d, al[mi], bh[2 * hh], bh[2 * hh + 1]);
                    }
                }
            }
        }
        __syncthreads();   // all warps done reading this buffer
        if (ck < 2) {
            prefetch_chunk(bufs[ck & 1], Ah_g, Al_g, Bh_g, Bl_g,
                           (ck + 2) * 32, block_row, M, tid);
            cp_commit();
        }
    }

    // --- epilogue ---
    const int qrow = lane >> 2;
    const int qcol = (lane & 3) * 2;
#pragma unroll
    for (int mi = 0; mi < 2; mi++) {
#pragma unroll
        for (int nj = 0; nj < 8; nj++) {
            const int col = warp_n * 64 + nj * 8 + qcol;
            float bx = 0.f, by = 0.f;
            if (HAS_BIAS) {
                float2 b2 = *reinterpret_cast<const float2*>(&bias[col]);
                bx = b2.x; by = b2.y;
            }
            const float* d = acc[mi][nj];
#pragma unroll
            for (int half = 0; half < 2; half++) {
                const int r = block_row + warp_m * 32 + mi * 16 + qrow + half * 8;
                if (r >= M) continue;
                float vx = d[half * 2 + 0] + bx;
                float vy = d[half * 2 + 1] + by;
                if (RELU_C) { vx = fmaxf(vx, 0.f); vy = fmaxf(vy, 0.f); }
                if (OUT_PLANES) {
                    __nv_bfloat16 hx, lx, hy, ly;
                    split_bf16(vx, hx, lx); split_bf16(vy, hy, ly);
                    *reinterpret_cast<__nv_bfloat162*>(&Ch[(size_t)r * 128 + col]) =
                        __nv_bfloat162(hx, hy);
                    *reinterpret_cast<__nv_bfloat162*>(&Cl[(size_t)r * 128 + col]) =
                        __nv_bfloat162(lx, ly);
                } else {
                    *reinterpret_cast<float2*>(&Cf[(size_t)r * ldc + col]) =
                        make_float2(vx, vy);
                }
            }
        }
    }
}

// Layer 1: h planes = relu(x @ W_in + b_in)  (planes in, planes out)
__global__ void __launch_bounds__(256, 2)
gemm_layer1(const float* __restrict__ b_in, int M)
{
    extern __shared__ char dynsmem[];
    gemm_tile_p<true, true, true>(g_xh, g_xl, g_wh, g_wl, b_in,
                                  nullptr, g_hh, g_hl, 0, blockIdx.x * 128, M,
                                  reinterpret_cast<Smem*>(dynsmem));
}

// Layer 2: y==0 -> h2 = h@W_self + b_self (fp32, pre-relu); y=1..8 -> hr slice
__global__ void __launch_bounds__(256, 2)
gemm_layer2(const float* __restrict__ b_self, int M)
{
    extern __shared__ char dynsmem[];
    Smem* bufs = reinterpret_cast<Smem*>(dynsmem);
    const int rel = blockIdx.y;
    if (rel == 0) {
        gemm_tile_p<true, false, false>(g_hh, g_hl,
                                        g_wh + (size_t)1 * HID * HID,
                                        g_wl + (size_t)1 * HID * HID,
                                        b_self, g_h2, nullptr, nullptr,
                                        128, blockIdx.x * 128, M, bufs);
    } else {
        gemm_tile_p<false, false, false>(g_hh, g_hl,
                                         g_wh + (size_t)(rel + 1) * HID * HID,
                                         g_wl + (size_t)(rel + 1) * HID * HID,
                                         nullptr, g_hr + (size_t)(rel - 1) * HID,
                                         nullptr, nullptr,
                                         RR * HID, blockIdx.x * 128, M, bufs);
    }
}

// Final: out = relu(h2) @ W_out + b_out  (relu already applied in h2 planes)
__global__ void __launch_bounds__(256, 2)
gemm_final(const float* __restrict__ b_out, float* __restrict__ out, int M)
{
    extern __shared__ char dynsmem[];
    gemm_tile_p<true, false, false>(g_h2h, g_h2l,
                                    g_wh + (size_t)10 * HID * HID,
                                    g_wl + (size_t)10 * HID * HID,
                                    b_out, out, nullptr, nullptr,
                                    128, blockIdx.x * 128, M,
                                    reinterpret_cast<Smem*>(dynsmem));
}

// ---------------------------------------------------------------------------
// Edge scatter: h2[dst] += w * hr[src][r]   (1 warp/edge, L2-resident atomics)
// ---------------------------------------------------------------------------
__global__ void __launch_bounds__(256)
scatter_kernel(const float* __restrict__ hr, const int* __restrict__ src,
               const int* __restrict__ dst, const float* __restrict__ w,
               float* __restrict__ h2)
{
    int e = (int)((blockIdx.x * blockDim.x + threadIdx.x) >> 5);
    if (e >= RR * EE) return;
    int lane = threadIdx.x & 31;

    int s = 0, d = 0; float wt = 0.f;
    if (lane == 0) { s = src[e]; d = dst[e]; wt = w[e]; }
    s  = __shfl_sync(0xffffffffu, s, 0);
    d  = __shfl_sync(0xffffffffu, d, 0);
    wt = __shfl_sync(0xffffffffu, wt, 0);
    int r = e / EE;

    float4 v = reinterpret_cast<const float4*>(hr + (size_t)s * (RR * HID) + r * HID)[lane];

    float* p = h2 + (size_t)d * HID + lane * 4;
    atomicAdd(p + 0, v.x * wt);
    atomicAdd(p + 1, v.y * wt);
    atomicAdd(p + 2, v.z * wt);
    atomicAdd(p + 3, v.w * wt);
}

// ---------------------------------------------------------------------------
// Launch
// ---------------------------------------------------------------------------
extern "C" void kernel_launch(void* const* d_in, const int* in_sizes, int n_in,
                              void* d_out, int out_size)
{
    // metadata order: x, edge_src, edge_dst, edge_w, W_in, b_in, W_rel,
    //                 W_self, b_self, W_out, b_out
    const float* x        = (const float*)d_in[0];
    const int*   edge_src = (const int*)  d_in[1];
    const int*   edge_dst = (const int*)  d_in[2];
    const float* edge_w   = (const float*)d_in[3];
    const float* W_in     = (const float*)d_in[4];
    const float* b_in     = (const float*)d_in[5];
    const float* W_rel    = (const float*)d_in[6];
    const float* W_self   = (const float*)d_in[7];
    const float* b_self   = (const float*)d_in[8];
    const float* W_out    = (const float*)d_in[9];
    const float* b_out    = (const float*)d_in[10];
    float* out = (float*)d_out;

    __nv_bfloat16 *wh, *wl, *xh, *xl, *h2h, *h2l;
    float *h2, *hr;
    {
        void* p = nullptr;
        cudaGetSymbolAddress(&p, g_wh);  wh  = (__nv_bfloat16*)p;
        cudaGetSymbolAddress(&p, g_wl);  wl  = (__nv_bfloat16*)p;
        cudaGetSymbolAddress(&p, g_xh);  xh  = (__nv_bfloat16*)p;
        cudaGetSymbolAddress(&p, g_xl);  xl  = (__nv_bfloat16*)p;
        cudaGetSymbolAddress(&p, g_h2h); h2h = (__nv_bfloat16*)p;
        cudaGetSymbolAddress(&p, g_h2l); h2l = (__nv_bfloat16*)p;
        cudaGetSymbolAddress(&p, g_h2);  h2  = (float*)p;
        cudaGetSymbolAddress(&p, g_hr);  hr  = (float*)p;
    }

    const size_t WSZ = (size_t)HID * HID;           // 16384
    const int gemm_grid = (NN + 127) / 128;         // 782
    const int SMEM2 = (int)(2 * sizeof(Smem));      // 75776 B

    cudaFuncSetAttribute(gemm_layer1, cudaFuncAttributeMaxDynamicSharedMemorySize, SMEM2);
    cudaFuncSetAttribute(gemm_layer2, cudaFuncAttributeMaxDynamicSharedMemorySize, SMEM2);
    cudaFuncSetAttribute(gemm_final,  cudaFuncAttributeMaxDynamicSharedMemorySize, SMEM2);

    // Precompute bf16 planes: x + all weights
    convert_planes<<<4096, 256>>>(x, xh, xl, (size_t)NN * HID / 4, 0);
    convert_planes<<<32, 256>>>(W_in,   wh,             wl,             WSZ / 4, 0);
    convert_planes<<<32, 256>>>(W_self, wh + WSZ,       wl + WSZ,       WSZ / 4, 0);
    convert_planes<<<128, 256>>>(W_rel, wh + 2 * WSZ,   wl + 2 * WSZ,   RR * WSZ / 4, 0);
    convert_planes<<<32, 256>>>(W_out,  wh + 10 * WSZ,  wl + 10 * WSZ,  WSZ / 4, 0);

    // Layer 1: h planes = relu(x @ W_in + b_in)
    gemm_layer1<<<gemm_grid, 256, SMEM2>>>(b_in, NN);

    // Layer 2: h2 = h@W_self + b_self (fp32), hr[:,r,:] = h@W_rel[r]
    gemm_layer2<<<dim3(gemm_grid, RR + 1), 256, SMEM2>>>(b_self, NN);

    // Scatter: h2[dst] += w * hr[src][r]
    {
        int blocks = (RR * EE * 32 + 255) / 256;    // 75000
        scatter_kernel<<<blocks, 256>>>(hr, edge_src, edge_dst, edge_w, h2);
    }

    // relu(h2) -> planes
    convert_planes<<<4096, 256>>>(h2, h2h, h2l, (size_t)NN * HID / 4, 1);

    // Output: out = relu(h2) @ W_out + b_out
    gemm_final<<<gemm_grid, 256, SMEM2>>>(b_out, out, NN);
}